// round 6
// baseline (speedup 1.0000x reference)
#include <cuda_runtime.h>
#include <cstdint>

#define BATCH 8
#define NPTS  32768
#define DIM   256
#define SPTS  64
#define NS    8
#define R2    16.0f
#define FCTAS 8                 // CTAs per batch (cluster size)
#define SEG   (NPTS/FCTAS)      // 4096 points per CTA
#define FBLK  128               // threads per FPS CTA
#define FPT   (SEG/FBLK)        // 32 points per thread
#define NGRP  (FPT/2)           // 16 f32x2 groups

// ---------------- scratch (no allocations allowed) ----------------
__device__ int   g_fps[BATCH*SPTS];
__device__ float g_scoor[BATCH*SPTS*3];
__device__ float g_dcoor[BATCH*SPTS*3];
__device__ float g_diffx[BATCH*SPTS*DIM];
__device__ float g_sampx[BATCH*SPTS*DIM];
__device__ float g_q[BATCH*SPTS*DIM];
__device__ float g_kT[BATCH*DIM*SPTS];   // k transposed: [b][c][j]

// ---------------- PTX helpers ----------------
__device__ __forceinline__ uint32_t smem_u32(const void* p) {
    uint32_t a;
    asm("{ .reg .u64 t; cvta.to.shared.u64 t, %1; cvt.u32.u64 %0, t; }" : "=r"(a) : "l"(p));
    return a;
}
__device__ __forceinline__ uint32_t mapa_rank(uint32_t a, uint32_t r) {
    uint32_t o;
    asm("mapa.shared::cluster.u32 %0, %1, %2;" : "=r"(o) : "r"(a), "r"(r));
    return o;
}
__device__ __forceinline__ void st_cluster_b64(uint32_t a, unsigned long long v) {
    asm volatile("st.shared::cluster.b64 [%0], %1;" :: "r"(a), "l"(v) : "memory");
}
__device__ __forceinline__ void st_cluster_f32(uint32_t a, float v) {
    asm volatile("st.shared::cluster.f32 [%0], %1;" :: "r"(a), "f"(v) : "memory");
}
__device__ __forceinline__ void st_cluster_release_b64(uint32_t a, unsigned long long v) {
    asm volatile("st.release.cluster.shared::cluster.b64 [%0], %1;" :: "r"(a), "l"(v) : "memory");
}
__device__ __forceinline__ unsigned long long ld_acquire_b64(uint32_t a) {
    unsigned long long v;
    asm volatile("ld.acquire.cluster.shared::cta.b64 %0, [%1];" : "=l"(v) : "r"(a) : "memory");
    return v;
}
#define CLUSTER_SYNC() do { \
    asm volatile("barrier.cluster.arrive.aligned;" ::: "memory"); \
    asm volatile("barrier.cluster.wait.aligned;" ::: "memory"); \
} while (0)

// f32x2 packed math
__device__ __forceinline__ unsigned long long f2x2(float a, float b) {
    unsigned long long r;
    asm("mov.b64 %0, {%1, %2};" : "=l"(r) : "r"(__float_as_uint(a)), "r"(__float_as_uint(b)));
    return r;
}
__device__ __forceinline__ unsigned long long add2(unsigned long long a, unsigned long long b) {
    unsigned long long r; asm("add.rn.f32x2 %0, %1, %2;" : "=l"(r) : "l"(a), "l"(b)); return r;
}
__device__ __forceinline__ unsigned long long mul2(unsigned long long a, unsigned long long b) {
    unsigned long long r; asm("mul.rn.f32x2 %0, %1, %2;" : "=l"(r) : "l"(a), "l"(b)); return r;
}
__device__ __forceinline__ unsigned long long fma2(unsigned long long a, unsigned long long b,
                                                   unsigned long long c) {
    unsigned long long r; asm("fma.rn.f32x2 %0, %1, %2, %3;" : "=l"(r) : "l"(a), "l"(b), "l"(c)); return r;
}
__device__ __forceinline__ void unpack2(unsigned long long v, float& lo, float& hi) {
    uint32_t l, h;
    asm("mov.b64 {%0, %1}, %2;" : "=r"(l), "=r"(h) : "l"(v));
    lo = __uint_as_float(l); hi = __uint_as_float(h);
}

// ---------------- K1: farthest point sampling ----------------
// 8-CTA cluster per batch, 128 threads/CTA (1 warp per SMSP), 32 pts/thread
// register-resident. Comm: sentinel-keyed DSMEM slot push (release) + poll.
// key = (distbits<<32) | (0x7fffffff - idx): u64 max == strict-> + lowest idx.
struct __align__(8) FpsSlot { unsigned long long key; unsigned long long xy; float z; float pad; };

__global__ void __cluster_dims__(FCTAS, 1, 1) __launch_bounds__(FBLK, 1)
fps_kernel(const float* __restrict__ coor) {
    const int b    = blockIdx.x / FCTAS;
    const int r    = blockIdx.x % FCTAS;
    const int tid  = threadIdx.x;
    const int lane = tid & 31;
    const int wid  = tid >> 5;

    __shared__ unsigned           s_v[4];
    __shared__ int                s_i[4];
    __shared__ unsigned long long s_xy[4];
    __shared__ float              s_z[4];
    __shared__ FpsSlot            c_slot[2][FCTAS];
    __shared__ int                s_bfar;
    __shared__ float              s_bc[3];

    const int gbase = r * SEG + tid * FPT;
    const float4* cp4 = (const float4*)(coor + ((size_t)b * NPTS + gbase) * 3);

    unsigned long long px2[NGRP], py2[NGRP], pz2[NGRP];
    float dist[FPT];
#pragma unroll
    for (int c = 0; c < 4; c++) {          // 4 chunks of 8 pts (6 float4 each)
        float f[24];
#pragma unroll
        for (int i = 0; i < 6; i++) {
            float4 v = cp4[c*6 + i];
            f[4*i+0] = v.x; f[4*i+1] = v.y; f[4*i+2] = v.z; f[4*i+3] = v.w;
        }
#pragma unroll
        for (int g = 0; g < 4; g++) {
            px2[c*4+g] = f2x2(f[6*g+0], f[6*g+3]);
            py2[c*4+g] = f2x2(f[6*g+1], f[6*g+4]);
            pz2[c*4+g] = f2x2(f[6*g+2], f[6*g+5]);
        }
    }
#pragma unroll
    for (int i = 0; i < FPT; i++) dist[i] = 1e10f;

    if (tid < 16) c_slot[tid >> 3][tid & 7].key = 0ull;   // sentinel init
    __syncthreads();
    CLUSTER_SYNC();           // sentinel init visible before any peer push

    float cx = coor[(size_t)b*NPTS*3 + 0];
    float cy = coor[(size_t)b*NPTS*3 + 1];
    float cz = coor[(size_t)b*NPTS*3 + 2];
    int far = 0;

    for (int it = 0; it < SPTS; it++) {
        if (r == 0 && tid == 0) {
            g_fps[b*SPTS + it] = far;
            g_scoor[(b*SPTS + it)*3 + 0] = cx;
            g_scoor[(b*SPTS + it)*3 + 1] = cy;
            g_scoor[(b*SPTS + it)*3 + 2] = cz;
        }
        if (it == SPTS - 1) break;

        const unsigned long long ncx = f2x2(-cx, -cx);
        const unsigned long long ncy = f2x2(-cy, -cy);
        const unsigned long long ncz = f2x2(-cz, -cz);

        float bv = -1.0f, bx = 0.f, by = 0.f, bz = 0.f;
        int   bi = 0;                       // local 0..FPT-1
#pragma unroll
        for (int j = 0; j < NGRP; j++) {
            unsigned long long dx = add2(px2[j], ncx);
            unsigned long long dy = add2(py2[j], ncy);
            unsigned long long dz = add2(pz2[j], ncz);
            unsigned long long d2 = mul2(dx, dx);
            d2 = fma2(dy, dy, d2);
            d2 = fma2(dz, dz, d2);
            float lo, hi;
            unpack2(d2, lo, hi);
            float xl, xh, yl, yh, zl, zh;    // reg-pair aliases, free
            unpack2(px2[j], xl, xh); unpack2(py2[j], yl, yh); unpack2(pz2[j], zl, zh);
            float nd0 = fminf(dist[2*j],   lo); dist[2*j]   = nd0;
            if (nd0 > bv) { bv = nd0; bi = 2*j;   bx = xl; by = yl; bz = zl; }
            float nd1 = fminf(dist[2*j+1], hi); dist[2*j+1] = nd1;
            if (nd1 > bv) { bv = nd1; bi = 2*j+1; bx = xh; by = yh; bz = zh; }
        }

        // warp argmax: dist>=0 so float bits monotone; lowest lane = lowest idx
        unsigned vb   = __float_as_uint(bv);
        unsigned vmax = __reduce_max_sync(0xffffffffu, vb);
        unsigned mk   = __ballot_sync(0xffffffffu, vb == vmax);
        if (lane == __ffs(mk) - 1) {
            s_v[wid]  = vmax;
            s_i[wid]  = gbase + bi;
            s_xy[wid] = f2x2(bx, by);
            s_z[wid]  = bz;
        }
        __syncthreads();

        const int p = it & 1;
        if (wid == 0) {
            unsigned v  = (lane < 4) ? s_v[lane] : 0u;
            unsigned vm = __reduce_max_sync(0xffffffffu, v);
            unsigned m2 = __ballot_sync(0xffffffffu, v == vm);
            int s2 = __ffs(m2) - 1;                  // lowest warp = lowest idx
            if (lane < FCTAS) {
                int fi2 = s_i[s2];
                unsigned long long key =
                    ((unsigned long long)vm << 32) | (unsigned)(0x7fffffff - fi2);
                uint32_t la = smem_u32(&c_slot[p][r]);
                uint32_t ra = mapa_rank(la, lane);
                st_cluster_b64(ra + 8,  s_xy[s2]);
                st_cluster_f32(ra + 16, s_z[s2]);
                st_cluster_release_b64(ra, key);     // also orders prior slot reset
            }
            // poll local slots: the key store IS the completion signal
            uint32_t pa = smem_u32(&c_slot[p][lane & 7]);
            unsigned long long kk = 1;
            do {
                if (lane < FCTAS) kk = ld_acquire_b64(pa);
            } while (!__all_sync(0xffffffffu, kk != 0ull));
            __syncwarp();
            if (lane == 0) {
                unsigned long long bk = c_slot[p][0].key;
                int bs_ = 0;
#pragma unroll
                for (int rr = 1; rr < FCTAS; rr++) {
                    unsigned long long k2 = c_slot[p][rr].key;
                    if (k2 > bk) { bk = k2; bs_ = rr; }
                }
                s_bfar = 0x7fffffff - (int)(unsigned)bk;
                float nx, ny;
                unpack2(c_slot[p][bs_].xy, nx, ny);
                s_bc[0] = nx; s_bc[1] = ny; s_bc[2] = c_slot[p][bs_].z;
#pragma unroll
                for (int rr = 0; rr < FCTAS; rr++)   // re-arm sentinel for it+2
                    c_slot[p][rr].key = 0ull;
            }
        }
        __syncthreads();
        far = s_bfar;
        cx = s_bc[0]; cy = s_bc[1]; cz = s_bc[2];
    }
    CLUSTER_SYNC();   // keep smem alive until all peer traffic has drained
}

// ---------------- K2: ball query + gather + maxpool ----------------
__global__ void __launch_bounds__(256) bq_kernel(const float* __restrict__ x,
                                                 const float* __restrict__ coor,
                                                 float* __restrict__ out1) {
    const int s  = blockIdx.x;
    const int b  = blockIdx.y;
    const int bs = b * SPTS + s;
    const int tid  = threadIdx.x;
    const int lane = tid & 31;
    const int w    = tid >> 5;

    __shared__ int s_hits[8][NS];
    __shared__ int s_cnt[8];
    __shared__ int s_nidx[NS];

    const float cx = g_scoor[bs*3+0], cy = g_scoor[bs*3+1], cz = g_scoor[bs*3+2];
    const float* cb = coor + (size_t)b * NPTS * 3;

    {
        const int segb = w * 4096;
        int cnt = 0;
        int nbr[NS];
        int j = segb + lane;
        float qx = cb[j*3], qy = cb[j*3+1], qz = cb[j*3+2];
        for (int jb = 0; jb < 4096 && cnt < NS; jb += 32) {
            float ax = qx, ay = qy, az = qz;
            int jn = segb + ((jb + 32 < 4096) ? jb + 32 : jb) + lane;
            qx = cb[jn*3]; qy = cb[jn*3+1]; qz = cb[jn*3+2];
            float dx = ax - cx, dy = ay - cy, dz = az - cz;
            float d2 = dx*dx + dy*dy + dz*dz;
            unsigned m = __ballot_sync(~0u, d2 < R2);
            while (m && cnt < NS) {
                int bit = __ffs(m) - 1;
                nbr[cnt++] = segb + jb + bit;
                m &= m - 1;
            }
        }
        if (lane == 0) {
            s_cnt[w] = cnt;
#pragma unroll
            for (int i = 0; i < NS; i++)
                if (i < cnt) s_hits[w][i] = nbr[i];
        }
    }
    __syncthreads();

    if (tid == 0) {
        int tot = 0;
#pragma unroll
        for (int ww = 0; ww < 8; ww++) {
            int c = s_cnt[ww];
#pragma unroll
            for (int i = 0; i < NS; i++)
                if (i < c && tot < NS) { s_nidx[tot] = s_hits[ww][i]; tot++; }
        }
        if (tot == 0) { s_nidx[0] = 0; tot = 1; }
        int f = s_nidx[0];
        for (; tot < NS; tot++) s_nidx[tot] = f;
    }
    __syncthreads();

    if (tid < NS) {
        int nj = s_nidx[tid];
        float ax = cb[nj*3+0] - cx;
        float ay = cb[nj*3+1] - cy;
        float az = cb[nj*3+2] - cz;
#pragma unroll
        for (int off = 4; off > 0; off >>= 1) {
            ax += __shfl_down_sync(0xffu, ax, off);
            ay += __shfl_down_sync(0xffu, ay, off);
            az += __shfl_down_sync(0xffu, az, off);
        }
        if (tid == 0) {
            g_dcoor[bs*3+0] = ax * 0.125f;
            g_dcoor[bs*3+1] = ay * 0.125f;
            g_dcoor[bs*3+2] = az * 0.125f;
        }
    }

    const int c = tid;
    const float* xb = x + (size_t)b * NPTS * DIM;
    int fidx = g_fps[bs];
    float sx = xb[(size_t)fidx * DIM + c];
    float m = -3.402823466e38f;
#pragma unroll
    for (int t = 0; t < NS; t++)
        m = fmaxf(m, xb[(size_t)s_nidx[t] * DIM + c]);
    out1[bs*DIM + c]    = m;             // sample_x + diff_x == global_x
    g_diffx[bs*DIM + c] = m - sx;
    g_sampx[bs*DIM + c] = sx;
}

// ---------------- K3: fused layernorm + q/k projection GEMM ----------------
__global__ void __launch_bounds__(256) gemmln_kernel(
        const float* __restrict__ Wq, const float* __restrict__ Wk,
        const float* __restrict__ gq, const float* __restrict__ bq,
        const float* __restrict__ gk, const float* __restrict__ bk) {
    const int rb = blockIdx.x, b = blockIdx.y, mat = blockIdx.z;
    const float* src = mat ? g_sampx : g_diffx;
    const float* W   = mat ? Wk      : Wq;
    const float* gg  = mat ? gk      : gq;
    const float* bb  = mat ? bk      : bq;

    __shared__ float As[8 * DIM];
    const int t = threadIdx.x;
    const int rowbase = b * SPTS + rb * 8;
#pragma unroll
    for (int i = 0; i < 8; i++)
        As[t + 256*i] = src[rowbase * DIM + t + 256*i];
    __syncthreads();

    {   // layernorm: warp w normalizes row w in place
        const int w = t >> 5, lane = t & 31;
        float4* r4 = (float4*)(As + w * DIM);
        float4 v0 = r4[lane*2], v1 = r4[lane*2+1];
        float sum = v0.x+v0.y+v0.z+v0.w + v1.x+v1.y+v1.z+v1.w;
        float sq  = v0.x*v0.x+v0.y*v0.y+v0.z*v0.z+v0.w*v0.w
                  + v1.x*v1.x+v1.y*v1.y+v1.z*v1.z+v1.w*v1.w;
#pragma unroll
        for (int off = 16; off > 0; off >>= 1) {
            sum += __shfl_xor_sync(~0u, sum, off);
            sq  += __shfl_xor_sync(~0u, sq,  off);
        }
        float mean = sum * (1.0f/256.0f);
        float var  = sq * (1.0f/256.0f) - mean * mean;
        float inv  = rsqrtf(var + 1e-5f);
        const float4* g4 = (const float4*)gg;
        const float4* b4 = (const float4*)bb;
        float4 G0 = g4[lane*2], G1 = g4[lane*2+1];
        float4 B0 = b4[lane*2], B1 = b4[lane*2+1];
        v0.x = (v0.x-mean)*inv*G0.x + B0.x;  v0.y = (v0.y-mean)*inv*G0.y + B0.y;
        v0.z = (v0.z-mean)*inv*G0.z + B0.z;  v0.w = (v0.w-mean)*inv*G0.w + B0.w;
        v1.x = (v1.x-mean)*inv*G1.x + B1.x;  v1.y = (v1.y-mean)*inv*G1.y + B1.y;
        v1.z = (v1.z-mean)*inv*G1.z + B1.z;  v1.w = (v1.w-mean)*inv*G1.w + B1.w;
        r4[lane*2]   = v0;
        r4[lane*2+1] = v1;
    }
    __syncthreads();

    const float4* W4 = (const float4*)(W + t * DIM);
    const float4* A4 = (const float4*)As;
    float acc[8] = {0,0,0,0,0,0,0,0};
#pragma unroll 8
    for (int c4 = 0; c4 < 64; c4++) {
        float4 w = W4[c4];
#pragma unroll
        for (int r = 0; r < 8; r++) {
            float4 a = A4[r*64 + c4];
            acc[r] += a.x*w.x + a.y*w.y + a.z*w.z + a.w*w.w;
        }
    }
    if (mat == 0) {
#pragma unroll
        for (int r = 0; r < 8; r++)
            g_q[(rowbase + r) * DIM + t] = acc[r];
    } else {
        // transposed k: g_kT[b][col=t][row]
        float4* o = (float4*)(g_kT + ((size_t)b * DIM + t) * SPTS + rb * 8);
        o[0] = make_float4(acc[0], acc[1], acc[2], acc[3]);
        o[1] = make_float4(acc[4], acc[5], acc[6], acc[7]);
    }
}

// ---------------- K4: attention + output2 ----------------
// CTA = (rowblock of 8, batch), 128 threads. kT staged in shared (coalesced),
// score loop runs entirely from LDS (conflict-free).
#define ATTN_SMEM_BYTES ((DIM*SPTS + 8*DIM + 8*64 + 192) * 4)
__global__ void __launch_bounds__(128) attn_kernel(float* __restrict__ out2) {
    extern __shared__ float sm[];
    float* kts   = sm;                    // [256][64] kT slice
    float* As    = kts + DIM * SPTS;      // 8 q rows
    float* s_att = As + 8 * DIM;          // 8x64 scores
    float* vs    = s_att + 8 * 64;        // 192 v values

    const int rb = blockIdx.x, b = blockIdx.y;
    const int t = threadIdx.x;
    const int rowbase = b * SPTS + rb * 8;

    {   // stage kT[b]: 16384 floats = 4096 float4, coalesced
        const float4* ksrc = (const float4*)(g_kT + (size_t)b * DIM * SPTS);
        float4* kdst = (float4*)kts;
#pragma unroll
        for (int i = 0; i < 32; i++)
            kdst[t + 128*i] = ksrc[t + 128*i];
    }
    {   // stage 8 q rows: 512 float4
        const float4* q4 = (const float4*)(g_q + rowbase * DIM);
        float4* a4 = (float4*)As;
#pragma unroll
        for (int i = 0; i < 4; i++)
            a4[t + 128*i] = q4[t + 128*i];
    }
    // v[b,i,j] = diff_coor[b,(3i+j)%64,(3i+j)/64] (torch view reinterp)
    vs[t] = g_dcoor[(b*SPTS + (t & 63))*3 + (t >> 6)];
    if (t < 64) { int i2 = t + 128; vs[i2] = g_dcoor[(b*SPTS + (i2 & 63))*3 + (i2 >> 6)]; }
    __syncthreads();

    const int cg = t & 15;         // 4 cols: 4cg..4cg+3
    const int r2 = t >> 4;         // row 0..7
    const float4* kt4 = (const float4*)kts + cg;
    const float*  qr  = As + r2 * DIM;
    float a0 = 0.f, a1 = 0.f, a2 = 0.f, a3 = 0.f;
#pragma unroll 8
    for (int c = 0; c < 256; c++) {
        float4 kv = kt4[c * 16];
        float  qv = qr[c];
        a0 += qv * kv.x; a1 += qv * kv.y; a2 += qv * kv.z; a3 += qv * kv.w;
    }
    const float sc = 0.0625f;      // 1/sqrt(256)
    *(float4*)(s_att + r2*64 + 4*cg) = make_float4(a0*sc, a1*sc, a2*sc, a3*sc);
    __syncthreads();

    const int w = t >> 5, lane = t & 31;
#pragma unroll
    for (int rr = 0; rr < 2; rr++) {
        int row = w * 2 + rr;
        float x0 = s_att[row*64 + lane];
        float x1 = s_att[row*64 + lane + 32];
        float mx = fmaxf(x0, x1);
#pragma unroll
        for (int off = 16; off > 0; off >>= 1) mx = fmaxf(mx, __shfl_xor_sync(~0u, mx, off));
        float e0 = expf(x0 - mx), e1 = expf(x1 - mx);
        float ssum = e0 + e1;
#pragma unroll
        for (int off = 16; off > 0; off >>= 1) ssum += __shfl_xor_sync(~0u, ssum, off);
        float rinv = 1.0f / ssum;
        float p0 = e0 * rinv, p1 = e1 * rinv;
        float c0 = p0 * vs[lane*3+0] + p1 * vs[(lane+32)*3+0];
        float c1 = p0 * vs[lane*3+1] + p1 * vs[(lane+32)*3+1];
        float c2 = p0 * vs[lane*3+2] + p1 * vs[(lane+32)*3+2];
#pragma unroll
        for (int off = 16; off > 0; off >>= 1) {
            c0 += __shfl_xor_sync(~0u, c0, off);
            c1 += __shfl_xor_sync(~0u, c1, off);
            c2 += __shfl_xor_sync(~0u, c2, off);
        }
        if (lane == 0) {
            int rowg = rowbase + row;
            out2[rowg*3+0] = g_scoor[rowg*3+0] + c0;
            out2[rowg*3+1] = g_scoor[rowg*3+1] + c1;
            out2[rowg*3+2] = g_scoor[rowg*3+2] + c2;
        }
    }
}

// ---------------- launcher ----------------
extern "C" void kernel_launch(void* const* d_in, const int* in_sizes, int n_in,
                              void* d_out, int out_size) {
    const float* x    = (const float*)d_in[0];
    const float* coor = (const float*)d_in[1];
    const float* Wq   = (const float*)d_in[2];
    const float* Wk   = (const float*)d_in[3];
    const float* lnqg = (const float*)d_in[4];
    const float* lnqb = (const float*)d_in[5];
    const float* lnkg = (const float*)d_in[6];
    const float* lnkb = (const float*)d_in[7];

    float* out1 = (float*)d_out;                 // [8,64,256]
    float* out2 = out1 + BATCH * SPTS * DIM;     // [8,64,3]

    cudaFuncSetAttribute(attn_kernel, cudaFuncAttributeMaxDynamicSharedMemorySize,
                         ATTN_SMEM_BYTES);

    fps_kernel<<<BATCH * FCTAS, FBLK>>>(coor);
    bq_kernel<<<dim3(SPTS, BATCH), 256>>>(x, coor, out1);
    gemmln_kernel<<<dim3(8, BATCH, 2), 256>>>(Wq, Wk, lnqg, lnqb, lnkg, lnkb);
    attn_kernel<<<dim3(8, BATCH), 128, ATTN_SMEM_BYTES>>>(out2);
}

// round 7
// speedup vs baseline: 1.0185x; 1.0185x over previous
#include <cuda_runtime.h>
#include <cstdint>

#define BATCH 8
#define NPTS  32768
#define DIM   256
#define SPTS  64
#define NS    8
#define R2    16.0f
#define FCTAS 8                 // CTAs per batch (cluster size)
#define SEG   (NPTS/FCTAS)      // 4096 points per CTA
#define FBLK  512
#define FPT   (SEG/FBLK)        // 8 points per thread

// ---------------- scratch (no allocations allowed) ----------------
__device__ int   g_fps[BATCH*SPTS];
__device__ float g_scoor[BATCH*SPTS*3];
__device__ float g_dcoor[BATCH*SPTS*3];
__device__ float g_diffx[BATCH*SPTS*DIM];
__device__ float g_sampx[BATCH*SPTS*DIM];
__device__ float g_q[BATCH*SPTS*DIM];
__device__ float g_kT[BATCH*DIM*SPTS];   // k transposed: [b][c][j]

// ---------------- PTX helpers ----------------
__device__ __forceinline__ uint32_t smem_u32(const void* p) {
    uint32_t a;
    asm("{ .reg .u64 t; cvta.to.shared.u64 t, %1; cvt.u32.u64 %0, t; }" : "=r"(a) : "l"(p));
    return a;
}
__device__ __forceinline__ uint32_t mapa_rank(uint32_t a, uint32_t r) {
    uint32_t o;
    asm("mapa.shared::cluster.u32 %0, %1, %2;" : "=r"(o) : "r"(a), "r"(r));
    return o;
}
__device__ __forceinline__ void st_cluster_b64(uint32_t a, unsigned long long v) {
    asm volatile("st.shared::cluster.b64 [%0], %1;" :: "r"(a), "l"(v) : "memory");
}
__device__ __forceinline__ void st_cluster_f32(uint32_t a, float v) {
    asm volatile("st.shared::cluster.f32 [%0], %1;" :: "r"(a), "f"(v) : "memory");
}
__device__ __forceinline__ void st_cluster_release_b64(uint32_t a, unsigned long long v) {
    asm volatile("st.release.cluster.shared::cluster.b64 [%0], %1;" :: "r"(a), "l"(v) : "memory");
}
__device__ __forceinline__ unsigned long long ld_acquire_b64(uint32_t a) {
    unsigned long long v;
    asm volatile("ld.acquire.cluster.shared::cta.b64 %0, [%1];" : "=l"(v) : "r"(a) : "memory");
    return v;
}
#define CLUSTER_SYNC() do { \
    asm volatile("barrier.cluster.arrive.aligned;" ::: "memory"); \
    asm volatile("barrier.cluster.wait.aligned;" ::: "memory"); \
} while (0)

// f32x2 packed math
__device__ __forceinline__ unsigned long long f2x2(float a, float b) {
    unsigned long long r;
    asm("mov.b64 %0, {%1, %2};" : "=l"(r) : "r"(__float_as_uint(a)), "r"(__float_as_uint(b)));
    return r;
}
__device__ __forceinline__ unsigned long long add2(unsigned long long a, unsigned long long b) {
    unsigned long long r; asm("add.rn.f32x2 %0, %1, %2;" : "=l"(r) : "l"(a), "l"(b)); return r;
}
__device__ __forceinline__ unsigned long long mul2(unsigned long long a, unsigned long long b) {
    unsigned long long r; asm("mul.rn.f32x2 %0, %1, %2;" : "=l"(r) : "l"(a), "l"(b)); return r;
}
__device__ __forceinline__ unsigned long long fma2(unsigned long long a, unsigned long long b,
                                                   unsigned long long c) {
    unsigned long long r; asm("fma.rn.f32x2 %0, %1, %2, %3;" : "=l"(r) : "l"(a), "l"(b), "l"(c)); return r;
}
__device__ __forceinline__ void unpack2(unsigned long long v, float& lo, float& hi) {
    uint32_t l, h;
    asm("mov.b64 {%0, %1}, %2;" : "=r"(l), "=r"(h) : "l"(v));
    lo = __uint_as_float(l); hi = __uint_as_float(h);
}

// ---------------- K1: farthest point sampling ----------------
// 8-CTA cluster per batch, 512 thr/CTA, 8 pts/thread register-resident.
// One barrier per iteration. 64-deep write-once slot ring (no reset, no 2nd
// barrier): warp0 pushes CTA winner to slot[it] of all peers (release); ALL
// warps poll their local slot[it] (acquire) and scan the 8 keys redundantly.
// key = (distbits<<32) | (0x7fffffff - idx): u64 max == strict-> + lowest idx.
struct __align__(8) FpsSlot { unsigned long long key; unsigned long long xy; float z; float pad; };

__global__ void __cluster_dims__(FCTAS, 1, 1) __launch_bounds__(FBLK, 1)
fps_kernel(const float* __restrict__ coor) {
    const int b    = blockIdx.x / FCTAS;
    const int r    = blockIdx.x % FCTAS;
    const int tid  = threadIdx.x;
    const int lane = tid & 31;
    const int wid  = tid >> 5;

    __shared__ unsigned           s_v[2][16];
    __shared__ int                s_i[2][16];
    __shared__ unsigned long long s_xy[2][16];
    __shared__ float              s_z[2][16];
    __shared__ FpsSlot            c_slot[SPTS][FCTAS];   // write-once ring

    const int gbase = r * SEG + tid * FPT;
    const float* cp = coor + ((size_t)b * NPTS + gbase) * 3;

    float fl[24];
    {
        const float4* c4 = (const float4*)cp;   // 96B per thread
#pragma unroll
        for (int i = 0; i < 6; i++) {
            float4 v = c4[i];
            fl[4*i+0] = v.x; fl[4*i+1] = v.y; fl[4*i+2] = v.z; fl[4*i+3] = v.w;
        }
    }
    unsigned long long px2[4], py2[4], pz2[4];
    float dist[FPT];
#pragma unroll
    for (int j = 0; j < 4; j++) {
        px2[j] = f2x2(fl[6*j+0], fl[6*j+3]);
        py2[j] = f2x2(fl[6*j+1], fl[6*j+4]);
        pz2[j] = f2x2(fl[6*j+2], fl[6*j+5]);
    }
#pragma unroll
    for (int i = 0; i < FPT; i++) dist[i] = 1e10f;

    c_slot[tid >> 3][tid & 7].key = 0ull;    // 512 threads = all 512 sentinels
    __syncthreads();
    CLUSTER_SYNC();           // sentinel init visible before any peer push

    float cx = coor[(size_t)b*NPTS*3 + 0];
    float cy = coor[(size_t)b*NPTS*3 + 1];
    float cz = coor[(size_t)b*NPTS*3 + 2];
    int far = 0;

    for (int it = 0; it < SPTS; it++) {
        if (r == 0 && tid == 0) {
            g_fps[b*SPTS + it] = far;
            g_scoor[(b*SPTS + it)*3 + 0] = cx;
            g_scoor[(b*SPTS + it)*3 + 1] = cy;
            g_scoor[(b*SPTS + it)*3 + 2] = cz;
        }
        if (it == SPTS - 1) break;

        const unsigned long long ncx = f2x2(-cx, -cx);
        const unsigned long long ncy = f2x2(-cy, -cy);
        const unsigned long long ncz = f2x2(-cz, -cz);

        float bv = -1.0f;
        int   bi = 0;                       // local 0..7
#pragma unroll
        for (int j = 0; j < 4; j++) {
            unsigned long long dx = add2(px2[j], ncx);
            unsigned long long dy = add2(py2[j], ncy);
            unsigned long long dz = add2(pz2[j], ncz);
            unsigned long long d2 = mul2(dx, dx);
            d2 = fma2(dy, dy, d2);
            d2 = fma2(dz, dz, d2);
            float lo, hi;
            unpack2(d2, lo, hi);
            float nd0 = fminf(dist[2*j],   lo); dist[2*j]   = nd0;
            if (nd0 > bv) { bv = nd0; bi = 2*j; }
            float nd1 = fminf(dist[2*j+1], hi); dist[2*j+1] = nd1;
            if (nd1 > bv) { bv = nd1; bi = 2*j+1; }
        }

        const int p = it & 1;
        // warp argmax: dist>=0 so float bits monotone; lowest lane = lowest idx
        unsigned vb   = __float_as_uint(bv);
        unsigned vmax = __reduce_max_sync(0xffffffffu, vb);
        unsigned mk   = __ballot_sync(0xffffffffu, vb == vmax);
        if (lane == __ffs(mk) - 1) {
            // mux candidate xyz (only on the winning lane)
            int jj = bi >> 1, h = bi & 1;
            unsigned long long mx2 = (jj & 2) ? ((jj & 1) ? px2[3] : px2[2]) : ((jj & 1) ? px2[1] : px2[0]);
            unsigned long long my2 = (jj & 2) ? ((jj & 1) ? py2[3] : py2[2]) : ((jj & 1) ? py2[1] : py2[0]);
            unsigned long long mz2 = (jj & 2) ? ((jj & 1) ? pz2[3] : pz2[2]) : ((jj & 1) ? pz2[1] : pz2[0]);
            float xl, xh, yl, yh, zl, zh;
            unpack2(mx2, xl, xh); unpack2(my2, yl, yh); unpack2(mz2, zl, zh);
            s_v[p][wid]  = vmax;
            s_i[p][wid]  = gbase + bi;
            s_xy[p][wid] = f2x2(h ? xh : xl, h ? yh : yl);
            s_z[p][wid]  = h ? zh : zl;
        }
        __syncthreads();                     // the ONLY barrier per iteration

        // every warp: CTA argmax over 16 warp winners (lowest warp = lowest idx)
        unsigned v  = (lane < 16) ? s_v[p][lane] : 0u;
        unsigned vm = __reduce_max_sync(0xffffffffu, v);
        unsigned m2 = __ballot_sync(0xffffffffu, v == vm);
        int s2 = __ffs(m2) - 1;

        if (wid == 0 && lane < FCTAS) {      // push CTA winner to slot[it] of all peers
            unsigned long long key =
                ((unsigned long long)vm << 32) | (unsigned)(0x7fffffff - s_i[p][s2]);
            uint32_t la = smem_u32(&c_slot[it][r]);
            uint32_t ra = mapa_rank(la, lane);
            st_cluster_b64(ra + 8,  s_xy[p][s2]);
            st_cluster_f32(ra + 16, s_z[p][s2]);
            st_cluster_release_b64(ra, key);
        }

        // every warp self-gates: poll local slot[it] keys (the store IS the signal)
        uint32_t pa = smem_u32(&c_slot[it][lane & 7]);
        unsigned long long kk = 1;
        do {
            if (lane < FCTAS) kk = ld_acquire_b64(pa);
        } while (!__all_sync(0xffffffffu, kk != 0ull));

        // every thread: scan 8 slots (u64 key max) — redundant but barrier-free
        unsigned long long bk = c_slot[it][0].key;
        int bs_ = 0;
#pragma unroll
        for (int rr = 1; rr < FCTAS; rr++) {
            unsigned long long k2 = c_slot[it][rr].key;
            if (k2 > bk) { bk = k2; bs_ = rr; }
        }
        far = 0x7fffffff - (int)(unsigned)bk;
        float nx, ny;
        unpack2(c_slot[it][bs_].xy, nx, ny);
        cx = nx; cy = ny; cz = c_slot[it][bs_].z;
    }
    CLUSTER_SYNC();   // keep smem alive until all peer traffic has drained
}

// ---------------- K2: ball query + gather + maxpool ----------------
__global__ void __launch_bounds__(256) bq_kernel(const float* __restrict__ x,
                                                 const float* __restrict__ coor,
                                                 float* __restrict__ out1) {
    const int s  = blockIdx.x;
    const int b  = blockIdx.y;
    const int bs = b * SPTS + s;
    const int tid  = threadIdx.x;
    const int lane = tid & 31;
    const int w    = tid >> 5;

    __shared__ int s_hits[8][NS];
    __shared__ int s_cnt[8];
    __shared__ int s_nidx[NS];

    const float cx = g_scoor[bs*3+0], cy = g_scoor[bs*3+1], cz = g_scoor[bs*3+2];
    const float* cb = coor + (size_t)b * NPTS * 3;

    {
        const int segb = w * 4096;
        int cnt = 0;
        int nbr[NS];
        int j = segb + lane;
        float qx = cb[j*3], qy = cb[j*3+1], qz = cb[j*3+2];
        for (int jb = 0; jb < 4096 && cnt < NS; jb += 32) {
            float ax = qx, ay = qy, az = qz;
            int jn = segb + ((jb + 32 < 4096) ? jb + 32 : jb) + lane;
            qx = cb[jn*3]; qy = cb[jn*3+1]; qz = cb[jn*3+2];
            float dx = ax - cx, dy = ay - cy, dz = az - cz;
            float d2 = dx*dx + dy*dy + dz*dz;
            unsigned m = __ballot_sync(~0u, d2 < R2);
            while (m && cnt < NS) {
                int bit = __ffs(m) - 1;
                nbr[cnt++] = segb + jb + bit;
                m &= m - 1;
            }
        }
        if (lane == 0) {
            s_cnt[w] = cnt;
#pragma unroll
            for (int i = 0; i < NS; i++)
                if (i < cnt) s_hits[w][i] = nbr[i];
        }
    }
    __syncthreads();

    if (tid == 0) {
        int tot = 0;
#pragma unroll
        for (int ww = 0; ww < 8; ww++) {
            int c = s_cnt[ww];
#pragma unroll
            for (int i = 0; i < NS; i++)
                if (i < c && tot < NS) { s_nidx[tot] = s_hits[ww][i]; tot++; }
        }
        if (tot == 0) { s_nidx[0] = 0; tot = 1; }
        int f = s_nidx[0];
        for (; tot < NS; tot++) s_nidx[tot] = f;
    }
    __syncthreads();

    if (tid < NS) {
        int nj = s_nidx[tid];
        float ax = cb[nj*3+0] - cx;
        float ay = cb[nj*3+1] - cy;
        float az = cb[nj*3+2] - cz;
#pragma unroll
        for (int off = 4; off > 0; off >>= 1) {
            ax += __shfl_down_sync(0xffu, ax, off);
            ay += __shfl_down_sync(0xffu, ay, off);
            az += __shfl_down_sync(0xffu, az, off);
        }
        if (tid == 0) {
            g_dcoor[bs*3+0] = ax * 0.125f;
            g_dcoor[bs*3+1] = ay * 0.125f;
            g_dcoor[bs*3+2] = az * 0.125f;
        }
    }

    const int c = tid;
    const float* xb = x + (size_t)b * NPTS * DIM;
    int fidx = g_fps[bs];
    float sx = xb[(size_t)fidx * DIM + c];
    float m = -3.402823466e38f;
#pragma unroll
    for (int t = 0; t < NS; t++)
        m = fmaxf(m, xb[(size_t)s_nidx[t] * DIM + c]);
    out1[bs*DIM + c]    = m;             // sample_x + diff_x == global_x
    g_diffx[bs*DIM + c] = m - sx;
    g_sampx[bs*DIM + c] = sx;
}

// ---------------- K3: fused layernorm + q/k projection GEMM ----------------
__global__ void __launch_bounds__(256) gemmln_kernel(
        const float* __restrict__ Wq, const float* __restrict__ Wk,
        const float* __restrict__ gq, const float* __restrict__ bq,
        const float* __restrict__ gk, const float* __restrict__ bk) {
    const int rb = blockIdx.x, b = blockIdx.y, mat = blockIdx.z;
    const float* src = mat ? g_sampx : g_diffx;
    const float* W   = mat ? Wk      : Wq;
    const float* gg  = mat ? gk      : gq;
    const float* bb  = mat ? bk      : bq;

    __shared__ float As[8 * DIM];
    const int t = threadIdx.x;
    const int rowbase = b * SPTS + rb * 8;
#pragma unroll
    for (int i = 0; i < 8; i++)
        As[t + 256*i] = src[rowbase * DIM + t + 256*i];
    __syncthreads();

    {   // layernorm: warp w normalizes row w in place
        const int w = t >> 5, lane = t & 31;
        float4* r4 = (float4*)(As + w * DIM);
        float4 v0 = r4[lane*2], v1 = r4[lane*2+1];
        float sum = v0.x+v0.y+v0.z+v0.w + v1.x+v1.y+v1.z+v1.w;
        float sq  = v0.x*v0.x+v0.y*v0.y+v0.z*v0.z+v0.w*v0.w
                  + v1.x*v1.x+v1.y*v1.y+v1.z*v1.z+v1.w*v1.w;
#pragma unroll
        for (int off = 16; off > 0; off >>= 1) {
            sum += __shfl_xor_sync(~0u, sum, off);
            sq  += __shfl_xor_sync(~0u, sq,  off);
        }
        float mean = sum * (1.0f/256.0f);
        float var  = sq * (1.0f/256.0f) - mean * mean;
        float inv  = rsqrtf(var + 1e-5f);
        const float4* g4 = (const float4*)gg;
        const float4* b4 = (const float4*)bb;
        float4 G0 = g4[lane*2], G1 = g4[lane*2+1];
        float4 B0 = b4[lane*2], B1 = b4[lane*2+1];
        v0.x = (v0.x-mean)*inv*G0.x + B0.x;  v0.y = (v0.y-mean)*inv*G0.y + B0.y;
        v0.z = (v0.z-mean)*inv*G0.z + B0.z;  v0.w = (v0.w-mean)*inv*G0.w + B0.w;
        v1.x = (v1.x-mean)*inv*G1.x + B1.x;  v1.y = (v1.y-mean)*inv*G1.y + B1.y;
        v1.z = (v1.z-mean)*inv*G1.z + B1.z;  v1.w = (v1.w-mean)*inv*G1.w + B1.w;
        r4[lane*2]   = v0;
        r4[lane*2+1] = v1;
    }
    __syncthreads();

    const float4* W4 = (const float4*)(W + t * DIM);
    const float4* A4 = (const float4*)As;
    float acc[8] = {0,0,0,0,0,0,0,0};
#pragma unroll 8
    for (int c4 = 0; c4 < 64; c4++) {
        float4 w = W4[c4];
#pragma unroll
        for (int r = 0; r < 8; r++) {
            float4 a = A4[r*64 + c4];
            acc[r] += a.x*w.x + a.y*w.y + a.z*w.z + a.w*w.w;
        }
    }
    if (mat == 0) {
#pragma unroll
        for (int r = 0; r < 8; r++)
            g_q[(rowbase + r) * DIM + t] = acc[r];
    } else {
        // transposed k: g_kT[b][col=t][row]
        float4* o = (float4*)(g_kT + ((size_t)b * DIM + t) * SPTS + rb * 8);
        o[0] = make_float4(acc[0], acc[1], acc[2], acc[3]);
        o[1] = make_float4(acc[4], acc[5], acc[6], acc[7]);
    }
}

// ---------------- K4: attention + output2 ----------------
// CTA = (rowblock of 8, batch), 128 threads. kT staged in shared (coalesced),
// score loop runs entirely from LDS (conflict-free).
#define ATTN_SMEM_BYTES ((DIM*SPTS + 8*DIM + 8*64 + 192) * 4)
__global__ void __launch_bounds__(128) attn_kernel(float* __restrict__ out2) {
    extern __shared__ float sm[];
    float* kts   = sm;                    // [256][64] kT slice
    float* As    = kts + DIM * SPTS;      // 8 q rows
    float* s_att = As + 8 * DIM;          // 8x64 scores
    float* vs    = s_att + 8 * 64;        // 192 v values

    const int rb = blockIdx.x, b = blockIdx.y;
    const int t = threadIdx.x;
    const int rowbase = b * SPTS + rb * 8;

    {   // stage kT[b]: 16384 floats = 4096 float4, coalesced
        const float4* ksrc = (const float4*)(g_kT + (size_t)b * DIM * SPTS);
        float4* kdst = (float4*)kts;
#pragma unroll
        for (int i = 0; i < 32; i++)
            kdst[t + 128*i] = ksrc[t + 128*i];
    }
    {   // stage 8 q rows: 512 float4
        const float4* q4 = (const float4*)(g_q + rowbase * DIM);
        float4* a4 = (float4*)As;
#pragma unroll
        for (int i = 0; i < 4; i++)
            a4[t + 128*i] = q4[t + 128*i];
    }
    // v[b,i,j] = diff_coor[b,(3i+j)%64,(3i+j)/64] (torch view reinterp)
    vs[t] = g_dcoor[(b*SPTS + (t & 63))*3 + (t >> 6)];
    if (t < 64) { int i2 = t + 128; vs[i2] = g_dcoor[(b*SPTS + (i2 & 63))*3 + (i2 >> 6)]; }
    __syncthreads();

    const int cg = t & 15;         // 4 cols: 4cg..4cg+3
    const int r2 = t >> 4;         // row 0..7
    const float4* kt4 = (const float4*)kts + cg;
    const float*  qr  = As + r2 * DIM;
    float a0 = 0.f, a1 = 0.f, a2 = 0.f, a3 = 0.f;
#pragma unroll 8
    for (int c = 0; c < 256; c++) {
        float4 kv = kt4[c * 16];
        float  qv = qr[c];
        a0 += qv * kv.x; a1 += qv * kv.y; a2 += qv * kv.z; a3 += qv * kv.w;
    }
    const float sc = 0.0625f;      // 1/sqrt(256)
    *(float4*)(s_att + r2*64 + 4*cg) = make_float4(a0*sc, a1*sc, a2*sc, a3*sc);
    __syncthreads();

    const int w = t >> 5, lane = t & 31;
#pragma unroll
    for (int rr = 0; rr < 2; rr++) {
        int row = w * 2 + rr;
        float x0 = s_att[row*64 + lane];
        float x1 = s_att[row*64 + lane + 32];
        float mx = fmaxf(x0, x1);
#pragma unroll
        for (int off = 16; off > 0; off >>= 1) mx = fmaxf(mx, __shfl_xor_sync(~0u, mx, off));
        float e0 = expf(x0 - mx), e1 = expf(x1 - mx);
        float ssum = e0 + e1;
#pragma unroll
        for (int off = 16; off > 0; off >>= 1) ssum += __shfl_xor_sync(~0u, ssum, off);
        float rinv = 1.0f / ssum;
        float p0 = e0 * rinv, p1 = e1 * rinv;
        float c0 = p0 * vs[lane*3+0] + p1 * vs[(lane+32)*3+0];
        float c1 = p0 * vs[lane*3+1] + p1 * vs[(lane+32)*3+1];
        float c2 = p0 * vs[lane*3+2] + p1 * vs[(lane+32)*3+2];
#pragma unroll
        for (int off = 16; off > 0; off >>= 1) {
            c0 += __shfl_xor_sync(~0u, c0, off);
            c1 += __shfl_xor_sync(~0u, c1, off);
            c2 += __shfl_xor_sync(~0u, c2, off);
        }
        if (lane == 0) {
            int rowg = rowbase + row;
            out2[rowg*3+0] = g_scoor[rowg*3+0] + c0;
            out2[rowg*3+1] = g_scoor[rowg*3+1] + c1;
            out2[rowg*3+2] = g_scoor[rowg*3+2] + c2;
        }
    }
}

// ---------------- launcher ----------------
extern "C" void kernel_launch(void* const* d_in, const int* in_sizes, int n_in,
                              void* d_out, int out_size) {
    const float* x    = (const float*)d_in[0];
    const float* coor = (const float*)d_in[1];
    const float* Wq   = (const float*)d_in[2];
    const float* Wk   = (const float*)d_in[3];
    const float* lnqg = (const float*)d_in[4];
    const float* lnqb = (const float*)d_in[5];
    const float* lnkg = (const float*)d_in[6];
    const float* lnkb = (const float*)d_in[7];

    float* out1 = (float*)d_out;                 // [8,64,256]
    float* out2 = out1 + BATCH * SPTS * DIM;     // [8,64,3]

    cudaFuncSetAttribute(attn_kernel, cudaFuncAttributeMaxDynamicSharedMemorySize,
                         ATTN_SMEM_BYTES);

    fps_kernel<<<BATCH * FCTAS, FBLK>>>(coor);
    bq_kernel<<<dim3(SPTS, BATCH), 256>>>(x, coor, out1);
    gemmln_kernel<<<dim3(8, BATCH, 2), 256>>>(Wq, Wk, lnqg, lnqb, lnkg, lnkb);
    attn_kernel<<<dim3(8, BATCH), 128, ATTN_SMEM_BYTES>>>(out2);
}

// round 8
// speedup vs baseline: 1.0793x; 1.0597x over previous
#include <cuda_runtime.h>
#include <cstdint>

#define BATCH 8
#define NPTS  32768
#define DIM   256
#define SPTS  64
#define NS    8
#define R2    16.0f
#define FCTAS 8                 // CTAs per batch (cluster size)
#define SEG   (NPTS/FCTAS)      // 4096 points per CTA
#define FBLK  512
#define FPT   (SEG/FBLK)        // 8 points per thread

// ---------------- scratch (no allocations allowed) ----------------
__device__ float g_dcoor[BATCH*SPTS*3];
__device__ float g_kT[BATCH*DIM*SPTS];   // k transposed: [b][c][j]

// dynamic smem layout (floats)
#define SQ_OFF   0                        // sq[8][256]
#define RA_OFF   (8*DIM)                  // region A: sdiff/ssamp, later kts[256][64]
#define SD_OFF   RA_OFF                   // sdiff[8][256]
#define SS_OFF   (RA_OFF + 8*DIM)         // ssamp[8][256]
#define KT_OFF   RA_OFF                   // kts[256][64] (aliases sdiff/ssamp)
#define VS_OFF   (RA_OFF + DIM*SPTS)      // vs[192]
#define AT_OFF   (VS_OFF + 192)           // s_att[8][64]
#define DYN_FLOATS (AT_OFF + 8*64)
#define DYN_BYTES  (DYN_FLOATS * 4)

// ---------------- PTX helpers ----------------
__device__ __forceinline__ uint32_t smem_u32(const void* p) {
    uint32_t a;
    asm("{ .reg .u64 t; cvta.to.shared.u64 t, %1; cvt.u32.u64 %0, t; }" : "=r"(a) : "l"(p));
    return a;
}
__device__ __forceinline__ uint32_t mapa_rank(uint32_t a, uint32_t r) {
    uint32_t o;
    asm("mapa.shared::cluster.u32 %0, %1, %2;" : "=r"(o) : "r"(a), "r"(r));
    return o;
}
__device__ __forceinline__ void st_cluster_b64(uint32_t a, unsigned long long v) {
    asm volatile("st.shared::cluster.b64 [%0], %1;" :: "r"(a), "l"(v) : "memory");
}
__device__ __forceinline__ void st_cluster_f32(uint32_t a, float v) {
    asm volatile("st.shared::cluster.f32 [%0], %1;" :: "r"(a), "f"(v) : "memory");
}
__device__ __forceinline__ void st_cluster_release_b64(uint32_t a, unsigned long long v) {
    asm volatile("st.release.cluster.shared::cluster.b64 [%0], %1;" :: "r"(a), "l"(v) : "memory");
}
__device__ __forceinline__ unsigned long long ld_acquire_b64(uint32_t a) {
    unsigned long long v;
    asm volatile("ld.acquire.cluster.shared::cta.b64 %0, [%1];" : "=l"(v) : "r"(a) : "memory");
    return v;
}
#define CLUSTER_SYNC() do { \
    asm volatile("barrier.cluster.arrive.aligned;" ::: "memory"); \
    asm volatile("barrier.cluster.wait.aligned;" ::: "memory"); \
} while (0)

// f32x2 packed math
__device__ __forceinline__ unsigned long long f2x2(float a, float b) {
    unsigned long long r;
    asm("mov.b64 %0, {%1, %2};" : "=l"(r) : "r"(__float_as_uint(a)), "r"(__float_as_uint(b)));
    return r;
}
__device__ __forceinline__ unsigned long long add2(unsigned long long a, unsigned long long b) {
    unsigned long long r; asm("add.rn.f32x2 %0, %1, %2;" : "=l"(r) : "l"(a), "l"(b)); return r;
}
__device__ __forceinline__ unsigned long long mul2(unsigned long long a, unsigned long long b) {
    unsigned long long r; asm("mul.rn.f32x2 %0, %1, %2;" : "=l"(r) : "l"(a), "l"(b)); return r;
}
__device__ __forceinline__ unsigned long long fma2(unsigned long long a, unsigned long long b,
                                                   unsigned long long c) {
    unsigned long long r; asm("fma.rn.f32x2 %0, %1, %2, %3;" : "=l"(r) : "l"(a), "l"(b), "l"(c)); return r;
}
__device__ __forceinline__ void unpack2(unsigned long long v, float& lo, float& hi) {
    uint32_t l, h;
    asm("mov.b64 {%0, %1}, %2;" : "=r"(l), "=r"(h) : "l"(v));
    lo = __uint_as_float(l); hi = __uint_as_float(h);
}

struct __align__(8) FpsSlot { unsigned long long key; unsigned long long xy; float z; float pad; };

// =====================================================================
// ONE fused kernel: FPS (R5 core) -> ball query -> gather/maxpool ->
// LN+GEMM (q&k in parallel halves) -> cluster sync -> attention.
// grid = 8 clusters x 8 CTAs; cluster rank r owns samples 8r..8r+7.
// =====================================================================
__global__ void __cluster_dims__(FCTAS, 1, 1) __launch_bounds__(FBLK, 1)
fused_kernel(const float* __restrict__ x, const float* __restrict__ coor,
             const float* __restrict__ Wq, const float* __restrict__ Wk,
             const float* __restrict__ gq, const float* __restrict__ bq,
             const float* __restrict__ gk, const float* __restrict__ bk,
             float* __restrict__ out1, float* __restrict__ out2) {
    extern __shared__ float dyn[];
    const int b    = blockIdx.x / FCTAS;
    const int r    = blockIdx.x % FCTAS;
    const int tid  = threadIdx.x;
    const int lane = tid & 31;
    const int wid  = tid >> 5;

    __shared__ unsigned           s_v[16];
    __shared__ int                s_i[16];
    __shared__ unsigned long long s_xy[16];
    __shared__ float              s_z[16];
    __shared__ FpsSlot            c_slot[2][FCTAS];
    __shared__ int                s_bfar;
    __shared__ float              s_bc[3];
    __shared__ int                fps_loc[SPTS];
    __shared__ float              scoor_loc[SPTS*3];
    __shared__ int                snidx[NS][NS];       // [local sample][neighbor]

    // ---------------- Phase 1: FPS (R5 core, local recording) ----------------
    {
        const int gbase = r * SEG + tid * FPT;
        const float* cp = coor + ((size_t)b * NPTS + gbase) * 3;
        float fl[24];
        {
            const float4* c4 = (const float4*)cp;
#pragma unroll
            for (int i = 0; i < 6; i++) {
                float4 v = c4[i];
                fl[4*i+0] = v.x; fl[4*i+1] = v.y; fl[4*i+2] = v.z; fl[4*i+3] = v.w;
            }
        }
        unsigned long long px2[4], py2[4], pz2[4];
        float dist[FPT];
#pragma unroll
        for (int j = 0; j < 4; j++) {
            px2[j] = f2x2(fl[6*j+0], fl[6*j+3]);
            py2[j] = f2x2(fl[6*j+1], fl[6*j+4]);
            pz2[j] = f2x2(fl[6*j+2], fl[6*j+5]);
        }
#pragma unroll
        for (int i = 0; i < FPT; i++) dist[i] = 1e10f;

        if (tid < 16) c_slot[tid >> 3][tid & 7].key = 0ull;   // sentinel init
        __syncthreads();
        CLUSTER_SYNC();           // sentinel init visible before any peer push

        float cx = coor[(size_t)b*NPTS*3 + 0];
        float cy = coor[(size_t)b*NPTS*3 + 1];
        float cz = coor[(size_t)b*NPTS*3 + 2];
        int far = 0;

        for (int it = 0; it < SPTS; it++) {
            if (tid == 0) {                  // EVERY CTA records locally
                fps_loc[it] = far;
                scoor_loc[it*3+0] = cx;
                scoor_loc[it*3+1] = cy;
                scoor_loc[it*3+2] = cz;
            }
            if (it == SPTS - 1) break;

            const unsigned long long ncx = f2x2(-cx, -cx);
            const unsigned long long ncy = f2x2(-cy, -cy);
            const unsigned long long ncz = f2x2(-cz, -cz);

            float bv = -1.0f;
            int   bi = 0;
#pragma unroll
            for (int j = 0; j < 4; j++) {
                unsigned long long dx = add2(px2[j], ncx);
                unsigned long long dy = add2(py2[j], ncy);
                unsigned long long dz = add2(pz2[j], ncz);
                unsigned long long d2 = mul2(dx, dx);
                d2 = fma2(dy, dy, d2);
                d2 = fma2(dz, dz, d2);
                float lo, hi;
                unpack2(d2, lo, hi);
                float nd0 = fminf(dist[2*j],   lo); dist[2*j]   = nd0;
                if (nd0 > bv) { bv = nd0; bi = 2*j; }
                float nd1 = fminf(dist[2*j+1], hi); dist[2*j+1] = nd1;
                if (nd1 > bv) { bv = nd1; bi = 2*j+1; }
            }
            // warp argmax: dist>=0, float bits monotone; lowest lane = lowest idx
            unsigned vb   = __float_as_uint(bv);
            unsigned vmax = __reduce_max_sync(0xffffffffu, vb);
            unsigned mk   = __ballot_sync(0xffffffffu, vb == vmax);
            if (lane == __ffs(mk) - 1) {
                int jj = bi >> 1, h = bi & 1;
                unsigned long long mx2 = (jj & 2) ? ((jj & 1) ? px2[3] : px2[2]) : ((jj & 1) ? px2[1] : px2[0]);
                unsigned long long my2 = (jj & 2) ? ((jj & 1) ? py2[3] : py2[2]) : ((jj & 1) ? py2[1] : py2[0]);
                unsigned long long mz2 = (jj & 2) ? ((jj & 1) ? pz2[3] : pz2[2]) : ((jj & 1) ? pz2[1] : pz2[0]);
                float xl, xh, yl, yh, zl, zh;
                unpack2(mx2, xl, xh); unpack2(my2, yl, yh); unpack2(mz2, zl, zh);
                s_v[wid]  = vmax;
                s_i[wid]  = gbase + bi;
                s_xy[wid] = f2x2(h ? xh : xl, h ? yh : yl);
                s_z[wid]  = h ? zh : zl;
            }
            __syncthreads();

            const int p = it & 1;
            if (wid == 0) {
                unsigned v  = (lane < 16) ? s_v[lane] : 0u;
                unsigned vm = __reduce_max_sync(0xffffffffu, v);
                unsigned m2 = __ballot_sync(0xffffffffu, v == vm);
                int s2 = __ffs(m2) - 1;              // lowest warp = lowest idx
                if (lane < FCTAS) {
                    unsigned long long key =
                        ((unsigned long long)vm << 32) | (unsigned)(0x7fffffff - s_i[s2]);
                    uint32_t la = smem_u32(&c_slot[p][r]);
                    uint32_t ra = mapa_rank(la, lane);
                    st_cluster_b64(ra + 8,  s_xy[s2]);
                    st_cluster_f32(ra + 16, s_z[s2]);
                    st_cluster_release_b64(ra, key);
                }
                uint32_t pa = smem_u32(&c_slot[p][lane & 7]);
                unsigned long long kk = 1;
                do {
                    if (lane < FCTAS) kk = ld_acquire_b64(pa);
                } while (!__all_sync(0xffffffffu, kk != 0ull));
                __syncwarp();
                if (lane == 0) {
                    unsigned long long bk = c_slot[p][0].key;
                    int bs_ = 0;
#pragma unroll
                    for (int rr = 1; rr < FCTAS; rr++) {
                        unsigned long long k2 = c_slot[p][rr].key;
                        if (k2 > bk) { bk = k2; bs_ = rr; }
                    }
                    s_bfar = 0x7fffffff - (int)(unsigned)bk;
                    float nx, ny;
                    unpack2(c_slot[p][bs_].xy, nx, ny);
                    s_bc[0] = nx; s_bc[1] = ny; s_bc[2] = c_slot[p][bs_].z;
#pragma unroll
                    for (int rr = 0; rr < FCTAS; rr++)
                        c_slot[p][rr].key = 0ull;
                }
            }
            __syncthreads();
            far = s_bfar;
            cx = s_bc[0]; cy = s_bc[1]; cz = s_bc[2];
        }
        CLUSTER_SYNC();   // drain in-flight peer slot traffic
    }

    // ---------------- Phase 2: ball query (warp w -> sample r*8+w) ----------------
    const float* cb = coor + (size_t)b * NPTS * 3;
    if (wid < NS) {
        const int sl = r * NS + wid;                 // local sample id in batch
        const float cx = scoor_loc[sl*3+0], cy = scoor_loc[sl*3+1], cz = scoor_loc[sl*3+2];
        int cnt = 0;
        int nbr[NS];
        for (int jb = 0; jb < NPTS && cnt < NS; jb += 32) {
            int j = jb + lane;
            float dx = cb[j*3+0] - cx;
            float dy = cb[j*3+1] - cy;
            float dz = cb[j*3+2] - cz;
            float d2 = dx*dx + dy*dy + dz*dz;
            unsigned m = __ballot_sync(~0u, d2 < R2);
            while (m && cnt < NS) {
                int bit = __ffs(m) - 1;
                nbr[cnt++] = jb + bit;
                m &= m - 1;
            }
        }
        if (lane == 0) {
            if (cnt == 0) { nbr[0] = 0; cnt = 1; }
            int f = nbr[0];
            for (int i2 = cnt; i2 < NS; i2++) nbr[i2] = f;
#pragma unroll
            for (int i2 = 0; i2 < NS; i2++) snidx[wid][i2] = nbr[i2];
        }
        __syncwarp();
        if (lane < NS) {                             // diff_coor mean
            int nj = snidx[wid][lane];
            float ax = cb[nj*3+0] - cx;
            float ay = cb[nj*3+1] - cy;
            float az = cb[nj*3+2] - cz;
#pragma unroll
            for (int off = 4; off > 0; off >>= 1) {
                ax += __shfl_down_sync(0xffu, ax, off);
                ay += __shfl_down_sync(0xffu, ay, off);
                az += __shfl_down_sync(0xffu, az, off);
            }
            if (lane == 0) {
                int bs = b * SPTS + sl;
                g_dcoor[bs*3+0] = ax * 0.125f;
                g_dcoor[bs*3+1] = ay * 0.125f;
                g_dcoor[bs*3+2] = az * 0.125f;
            }
        }
    }
    __syncthreads();

    // ---------------- Phase 3: gather + maxpool (8 samples x 256 ch) ----------------
    {
        const float* xb = x + (size_t)b * NPTS * DIM;
#pragma unroll
        for (int rd = 0; rd < 4; rd++) {
            int u  = rd * FBLK + tid;                // 0..2047
            int si = u >> 8;                         // 0..7
            int c  = u & 255;
            int sl = r * NS + si;
            float sx = xb[(size_t)fps_loc[sl] * DIM + c];
            float m = -3.402823466e38f;
#pragma unroll
            for (int t2 = 0; t2 < NS; t2++)
                m = fmaxf(m, xb[(size_t)snidx[si][t2] * DIM + c]);
            out1[(b * SPTS + sl) * DIM + c] = m;     // sample_x + diff_x == global_x
            dyn[SD_OFF + si*DIM + c] = m - sx;
            dyn[SS_OFF + si*DIM + c] = sx;
        }
    }
    __syncthreads();

    // ---------------- Phase 4: LN + GEMM (half 0 = q, half 1 = k) ----------------
    {
        const int half = tid >> 8;                   // 0 or 1
        const int t    = tid & 255;
        float* src = dyn + (half ? SS_OFF : SD_OFF);
        const float* W  = half ? Wk : Wq;
        const float* gg = half ? gk : gq;
        const float* bb = half ? bk : bq;

        {   // layernorm: warp (t>>5) normalizes row (t>>5) of its half, in place
            const int w = t >> 5, ln = t & 31;
            float4* r4 = (float4*)(src + w * DIM);
            float4 v0 = r4[ln*2], v1 = r4[ln*2+1];
            float sum = v0.x+v0.y+v0.z+v0.w + v1.x+v1.y+v1.z+v1.w;
            float sq  = v0.x*v0.x+v0.y*v0.y+v0.z*v0.z+v0.w*v0.w
                      + v1.x*v1.x+v1.y*v1.y+v1.z*v1.z+v1.w*v1.w;
#pragma unroll
            for (int off = 16; off > 0; off >>= 1) {
                sum += __shfl_xor_sync(~0u, sum, off);
                sq  += __shfl_xor_sync(~0u, sq,  off);
            }
            float mean = sum * (1.0f/256.0f);
            float var  = sq * (1.0f/256.0f) - mean * mean;
            float inv  = rsqrtf(var + 1e-5f);
            const float4* g4 = (const float4*)gg;
            const float4* b4 = (const float4*)bb;
            float4 G0 = g4[ln*2], G1 = g4[ln*2+1];
            float4 B0 = b4[ln*2], B1 = b4[ln*2+1];
            v0.x = (v0.x-mean)*inv*G0.x + B0.x;  v0.y = (v0.y-mean)*inv*G0.y + B0.y;
            v0.z = (v0.z-mean)*inv*G0.z + B0.z;  v0.w = (v0.w-mean)*inv*G0.w + B0.w;
            v1.x = (v1.x-mean)*inv*G1.x + B1.x;  v1.y = (v1.y-mean)*inv*G1.y + B1.y;
            v1.z = (v1.z-mean)*inv*G1.z + B1.z;  v1.w = (v1.w-mean)*inv*G1.w + B1.w;
            r4[ln*2]   = v0;
            r4[ln*2+1] = v1;
        }
        __syncthreads();

        const float4* W4 = (const float4*)(W + t * DIM);
        const float4* A4 = (const float4*)src;
        float acc[8] = {0,0,0,0,0,0,0,0};
#pragma unroll 8
        for (int c4 = 0; c4 < 64; c4++) {
            float4 w = W4[c4];
#pragma unroll
            for (int rr = 0; rr < 8; rr++) {
                float4 a = A4[rr*64 + c4];
                acc[rr] += a.x*w.x + a.y*w.y + a.z*w.z + a.w*w.w;
            }
        }
        if (half == 0) {
#pragma unroll
            for (int rr = 0; rr < 8; rr++)
                dyn[SQ_OFF + rr*DIM + t] = acc[rr];  // q stays in smem
        } else {
            float4* o = (float4*)(g_kT + ((size_t)b * DIM + t) * SPTS + r * 8);
            o[0] = make_float4(acc[0], acc[1], acc[2], acc[3]);
            o[1] = make_float4(acc[4], acc[5], acc[6], acc[7]);
        }
    }
    __threadfence();
    CLUSTER_SYNC();        // g_kT / g_dcoor visible cluster-wide

    // ---------------- Phase 5: attention for rows r*8..r*8+7 ----------------
    {
        float* kts   = dyn + KT_OFF;                 // [256][64] (aliases sdiff/ssamp)
        float* sq    = dyn + SQ_OFF;
        float* vs    = dyn + VS_OFF;
        float* s_att = dyn + AT_OFF;

        __syncthreads();                             // all reads of sdiff/ssamp done
        {   // stage kT[b]: 4096 float4, coalesced
            const float4* ksrc = (const float4*)(g_kT + (size_t)b * DIM * SPTS);
            float4* kdst = (float4*)kts;
#pragma unroll
            for (int i = 0; i < 8; i++)
                kdst[tid + FBLK*i] = ksrc[tid + FBLK*i];
        }
        // v[b,i,j] = diff_coor[b,(3i+j)%64,(3i+j)/64] (torch view reinterp)
        if (tid < 192) vs[tid] = g_dcoor[(b*SPTS + (tid & 63))*3 + (tid >> 6)];
        __syncthreads();

        const int j  = tid & 63;                     // k column
        const int r2 = tid >> 6;                     // row 0..7
        const float* qr = sq + r2 * DIM;
        float a = 0.f;
#pragma unroll 8
        for (int c = 0; c < 256; c++)
            a += qr[c] * kts[c*64 + j];
        s_att[r2*64 + j] = a * 0.0625f;              // 1/sqrt(256)
        __syncthreads();

        if (wid < 8) {
            const int row = wid;
            float x0 = s_att[row*64 + lane];
            float x1 = s_att[row*64 + lane + 32];
            float mx = fmaxf(x0, x1);
#pragma unroll
            for (int off = 16; off > 0; off >>= 1) mx = fmaxf(mx, __shfl_xor_sync(~0u, mx, off));
            float e0 = expf(x0 - mx), e1 = expf(x1 - mx);
            float ssum = e0 + e1;
#pragma unroll
            for (int off = 16; off > 0; off >>= 1) ssum += __shfl_xor_sync(~0u, ssum, off);
            float rinv = 1.0f / ssum;
            float p0 = e0 * rinv, p1 = e1 * rinv;
            float c0 = p0 * vs[lane*3+0] + p1 * vs[(lane+32)*3+0];
            float c1 = p0 * vs[lane*3+1] + p1 * vs[(lane+32)*3+1];
            float c2 = p0 * vs[lane*3+2] + p1 * vs[(lane+32)*3+2];
#pragma unroll
            for (int off = 16; off > 0; off >>= 1) {
                c0 += __shfl_xor_sync(~0u, c0, off);
                c1 += __shfl_xor_sync(~0u, c1, off);
                c2 += __shfl_xor_sync(~0u, c2, off);
            }
            if (lane == 0) {
                int sl   = r * 8 + row;
                int rowg = b * SPTS + sl;
                out2[rowg*3+0] = scoor_loc[sl*3+0] + c0;
                out2[rowg*3+1] = scoor_loc[sl*3+1] + c1;
                out2[rowg*3+2] = scoor_loc[sl*3+2] + c2;
            }
        }
    }
}

// ---------------- launcher ----------------
extern "C" void kernel_launch(void* const* d_in, const int* in_sizes, int n_in,
                              void* d_out, int out_size) {
    const float* x    = (const float*)d_in[0];
    const float* coor = (const float*)d_in[1];
    const float* Wq   = (const float*)d_in[2];
    const float* Wk   = (const float*)d_in[3];
    const float* lnqg = (const float*)d_in[4];
    const float* lnqb = (const float*)d_in[5];
    const float* lnkg = (const float*)d_in[6];
    const float* lnkb = (const float*)d_in[7];

    float* out1 = (float*)d_out;                 // [8,64,256]
    float* out2 = out1 + BATCH * SPTS * DIM;     // [8,64,3]

    cudaFuncSetAttribute(fused_kernel, cudaFuncAttributeMaxDynamicSharedMemorySize,
                         DYN_BYTES);

    fused_kernel<<<BATCH * FCTAS, FBLK, DYN_BYTES>>>(
        x, coor, Wq, Wk, lnqg, lnqb, lnkg, lnkb, out1, out2);
}